// round 4
// baseline (speedup 1.0000x reference)
#include <cuda_runtime.h>
#include <cuda_fp16.h>

typedef unsigned long long ull;

#define Bsz 1024
#define Tsz 512
#define Isz 128
#define Hsz 256
#define Osz 64
#define NB  8
#define NTHR 256
#define NCTA (Bsz / NB)   // 128

// ---------------- weight scratch (fp16, k-pair packed, column-major over rows) ----
// Layout: g_W*[kp * ROWS + row] = half2( W[row][2kp], W[row][2kp+1] )
__device__ __half2 g_Wih[(Isz / 2) * 768];   // 49152
__device__ __half2 g_Wt [(Isz / 2) * Hsz];   // 16384
__device__ __half2 g_Whh[(Hsz / 2) * 768];   // 98304
__device__ __half2 g_Wog[(Hsz / 2) * 128];   // 16384  (rows 0..63 = Wo, 64..127 = Wg)

// ---------------- packed f32x2 helpers ------------------------------------------
__device__ __forceinline__ ull fma2(ull a, ull b, ull c) {
    ull d;
    asm("fma.rn.f32x2 %0, %1, %2, %3;" : "=l"(d) : "l"(a), "l"(b), "l"(c));
    return d;
}
__device__ __forceinline__ float2 upk(ull v) {
    float2 r;
    asm("mov.b64 {%0, %1}, %2;" : "=f"(r.x), "=f"(r.y) : "l"(v));
    return r;
}
__device__ __forceinline__ ull h2f2(__half2 h) {
    float2 f = __half22float2(h);
    ull r;
    asm("mov.b64 %0, {%1, %2};" : "=l"(r) : "f"(f.x), "f"(f.y));
    return r;
}
__device__ __forceinline__ float sigmf(float x) { return 1.0f / (1.0f + __expf(-x)); }
__device__ __forceinline__ float tanh_f(float x) {
    float a = fabsf(x);
    float e = __expf(-2.0f * a);
    float r = (1.0f - e) / (1.0f + e);
    return copysignf(r, x);
}

// ---------------- weight prep: fp32 -> packed fp16 layouts ----------------------
__global__ void prep_weights(const float* __restrict__ Wih,
                             const float* __restrict__ Whh,
                             const float* __restrict__ Wt,
                             const float* __restrict__ Wo,
                             const float* __restrict__ Wg) {
    int i = blockIdx.x * blockDim.x + threadIdx.x;
    const int N1 = (Isz / 2) * 768;
    const int N2 = (Isz / 2) * Hsz;
    const int N3 = (Hsz / 2) * 768;
    const int N4 = (Hsz / 2) * 128;
    if (i < N1) {
        int kp = i / 768, r = i % 768;
        g_Wih[i] = __floats2half2_rn(Wih[r * Isz + 2 * kp], Wih[r * Isz + 2 * kp + 1]);
        return;
    }
    i -= N1;
    if (i < N2) {
        int kp = i / Hsz, r = i % Hsz;
        g_Wt[i] = __floats2half2_rn(Wt[r * Isz + 2 * kp], Wt[r * Isz + 2 * kp + 1]);
        return;
    }
    i -= N2;
    if (i < N3) {
        int kp = i / 768, r = i % 768;
        g_Whh[i] = __floats2half2_rn(Whh[r * Hsz + 2 * kp], Whh[r * Hsz + 2 * kp + 1]);
        return;
    }
    i -= N3;
    if (i < N4) {
        int kp = i / 128, o = i % 128;
        const float* src = (o < 64) ? (Wo + (size_t)o * Hsz) : (Wg + (size_t)(o - 64) * Hsz);
        g_Wog[(size_t)kp * 128 + o] = __floats2half2_rn(src[2 * kp], src[2 * kp + 1]);
    }
}

// ---------------- persistent GRU scan: 1 CTA = 8 batch rows, no inter-CTA sync ---
__global__ void __launch_bounds__(NTHR, 1) gru_scan(
    const float* __restrict__ x,   const float* __restrict__ h0,
    const float* __restrict__ b_ih, const float* __restrict__ b_hh,
    const float* __restrict__ bt,  const float* __restrict__ bo,
    const float* __restrict__ bg,  float* __restrict__ out)
{
    __shared__ __align__(16) float hv_s[2][NB][Hsz];  // [0]=h, [1]=h_new + ti
    __shared__ __align__(16) float x_s[NB][Isz];
    __shared__ float red[2][128][NB + 1];              // +1 pad: conflict-free STS

    const int tid = threadIdx.x;
    const int j   = tid;              // hidden unit owned by this thread (0..255)
    const int b0  = blockIdx.x * NB;
    const int o   = tid & 127;        // output-proj row (0..63 Wo, 64..127 Wg)
    const int kh  = tid >> 7;         // k-half for phase D

    { // load h0 tile: [8][256]
        int b = tid >> 5, k0 = (tid & 31) * 8;
        const float4* p = (const float4*)(h0 + (size_t)(b0 + b) * Hsz + k0);
        *(float4*)&hv_s[0][b][k0]     = p[0];
        *(float4*)&hv_s[0][b][k0 + 4] = p[1];
    }

    const float br  = b_ih[j], bz = b_ih[Hsz + j], bn = b_ih[2 * Hsz + j];
    const float hbr = b_hh[j], hbz = b_hh[Hsz + j], hbn = b_hh[2 * Hsz + j];
    const float btj = bt[j];
    float biasD = 0.0f;
    if (tid < 128) biasD = (tid < 64) ? bo[tid] : bg[tid - 64];

    float oacc[NB];
#pragma unroll
    for (int b = 0; b < NB; ++b) oacc[b] = 0.0f;

    for (int t = 0; t < Tsz; ++t) {
        { // stage x[:, t, :] into smem
            int b = tid >> 5, k0 = (tid & 31) * 4;
            const float4* p = (const float4*)(x + ((size_t)(b0 + b) * Tsz + t) * Isz + k0);
            *(float4*)&x_s[b][k0] = *p;
        }
        __syncthreads();  // S1: x ready, h visible

        // ---- Phase A: input-side matvecs (xi r/z/n + transform), K=128 ----
        ull aR[NB], aZ[NB], aN[NB], aT[NB];
#pragma unroll
        for (int b = 0; b < NB; ++b) { aR[b] = 0ULL; aZ[b] = 0ULL; aN[b] = 0ULL; aT[b] = 0ULL; }
#pragma unroll 4
        for (int kp = 0; kp < Isz / 2; ++kp) {
            ull wr = h2f2(__ldg(g_Wih + kp * 768 + j));
            ull wz = h2f2(__ldg(g_Wih + kp * 768 + 256 + j));
            ull wn = h2f2(__ldg(g_Wih + kp * 768 + 512 + j));
            ull wt = h2f2(__ldg(g_Wt  + kp * Hsz + j));
#pragma unroll
            for (int b = 0; b < NB; ++b) {
                ull xv = *(const ull*)&x_s[b][2 * kp];
                aR[b] = fma2(wr, xv, aR[b]);
                aZ[b] = fma2(wz, xv, aZ[b]);
                aN[b] = fma2(wn, xv, aN[b]);
                aT[b] = fma2(wt, xv, aT[b]);
            }
        }
        float xr[NB], xz[NB], xn[NB], xt[NB];
#pragma unroll
        for (int b = 0; b < NB; ++b) {
            float2 f;
            f = upk(aR[b]); xr[b] = f.x + f.y + br;
            f = upk(aZ[b]); xz[b] = f.x + f.y + bz;
            f = upk(aN[b]); xn[b] = f.x + f.y + bn;
            f = upk(aT[b]); xt[b] = f.x + f.y + btj;
        }

        // ---- Phase B: recurrent matvec hh = W_hh . h, K=256 ----
        ull hR[NB], hZ[NB], hN[NB];
#pragma unroll
        for (int b = 0; b < NB; ++b) { hR[b] = 0ULL; hZ[b] = 0ULL; hN[b] = 0ULL; }
#pragma unroll 4
        for (int kp = 0; kp < Hsz / 2; ++kp) {
            ull wr = h2f2(__ldg(g_Whh + kp * 768 + j));
            ull wz = h2f2(__ldg(g_Whh + kp * 768 + 256 + j));
            ull wn = h2f2(__ldg(g_Whh + kp * 768 + 512 + j));
#pragma unroll
            for (int b = 0; b < NB; ++b) {
                ull hv = *(const ull*)&hv_s[0][b][2 * kp];
                hR[b] = fma2(wr, hv, hR[b]);
                hZ[b] = fma2(wz, hv, hZ[b]);
                hN[b] = fma2(wn, hv, hN[b]);
            }
        }
        __syncthreads();  // S2: all reads of h done before C overwrites

        // ---- Phase C: gates + state update (all in registers, unit j) ----
#pragma unroll
        for (int b = 0; b < NB; ++b) {
            float2 f;
            f = upk(hR[b]); float r = sigmf(xr[b] + f.x + f.y + hbr);
            f = upk(hZ[b]); float z = sigmf(xz[b] + f.x + f.y + hbz);
            f = upk(hN[b]); float n = tanh_f(xn[b] + r * (f.x + f.y + hbn));
            float hp   = hv_s[0][b][j];
            float hnew = n + z * (hp - n);
            hv_s[0][b][j] = hnew;
            float ti = xt[b] * sigmf(xt[b]);   // silu
            hv_s[1][b][j] = hnew + ti;
        }
        __syncthreads();  // S3: h_new / v ready

        // ---- Phase D: proj = Wo.(h+ti)+bo, gate = sigma(Wg.h+bg), split-K=2 ----
        {
            const int sel = (o < 64) ? 1 : 0;   // Wo reads v, Wg reads h
            ull acc[NB];
#pragma unroll
            for (int b = 0; b < NB; ++b) acc[b] = 0ULL;
#pragma unroll 4
            for (int kk = 0; kk < 64; ++kk) {
                int kp = kh * 64 + kk;
                ull w = h2f2(__ldg(g_Wog + kp * 128 + o));
#pragma unroll
                for (int b = 0; b < NB; ++b) {
                    ull sv = *(const ull*)&hv_s[sel][b][2 * kp];
                    acc[b] = fma2(w, sv, acc[b]);
                }
            }
#pragma unroll
            for (int b = 0; b < NB; ++b) {
                float2 f = upk(acc[b]);
                red[kh][o][b] = f.x + f.y;
            }
        }
        __syncthreads();  // S4
        if (tid < 128) {
#pragma unroll
            for (int b = 0; b < NB; ++b)
                red[0][tid][b] = red[0][tid][b] + red[1][tid][b] + biasD;
        }
        __syncthreads();  // S5
        if (tid < 64) {
#pragma unroll
            for (int b = 0; b < NB; ++b)
                oacc[b] += red[0][tid][b] * sigmf(red[0][64 + tid][b]);
        }
        // red reuse next step is fenced by S1..S3
    }

    if (tid < 64) {
        const float inv = 1.0f / (float)Tsz;
#pragma unroll
        for (int b = 0; b < NB; ++b)
            out[(size_t)(b0 + b) * Osz + tid] = oacc[b] * inv;
    }
}

// ---------------- launch ---------------------------------------------------------
extern "C" void kernel_launch(void* const* d_in, const int* in_sizes, int n_in,
                              void* d_out, int out_size) {
    const float* x    = (const float*)d_in[0];
    const float* h0   = (const float*)d_in[1];
    const float* W_ih = (const float*)d_in[2];
    const float* b_ih = (const float*)d_in[3];
    const float* W_hh = (const float*)d_in[4];
    const float* b_hh = (const float*)d_in[5];
    const float* Wt   = (const float*)d_in[6];
    const float* bt   = (const float*)d_in[7];
    const float* Wo   = (const float*)d_in[8];
    const float* bo   = (const float*)d_in[9];
    const float* Wg   = (const float*)d_in[10];
    const float* bg   = (const float*)d_in[11];
    float* out = (float*)d_out;

    const int total = (Isz / 2) * 768 + (Isz / 2) * Hsz + (Hsz / 2) * 768 + (Hsz / 2) * 128;
    prep_weights<<<(total + 255) / 256, 256>>>(W_ih, W_hh, Wt, Wo, Wg);
    gru_scan<<<NCTA, NTHR>>>(x, h0, b_ih, b_hh, bt, bo, bg, out);
}

// round 5
// speedup vs baseline: 1.1606x; 1.1606x over previous
#include <cuda_runtime.h>

typedef unsigned long long ull;

#define Bsz 1024
#define Tsz 512
#define Isz 128
#define Hsz 256
#define Osz 64
#define NB  8
#define NTHR 256
#define NCTA (Bsz / NB)   // 128

// ---------------- weight scratch: fp32, float4 k-packed, column-major over rows --
// g_W*4[kp2 * ROWS + row] = float4(W[row][4kp2], .., W[row][4kp2+3])
__device__ float4 g_Wih4[32 * 768];   // 393 KB
__device__ float4 g_Wt4 [32 * 256];   // 131 KB
__device__ float4 g_Whh4[64 * 768];   // 786 KB
__device__ float4 g_Wog4[64 * 128];   // 131 KB (rows 0..63 = Wo, 64..127 = Wg)

// ---------------- helpers --------------------------------------------------------
__device__ __forceinline__ ull fma2(ull a, ull b, ull c) {
    ull d;
    asm("fma.rn.f32x2 %0, %1, %2, %3;" : "=l"(d) : "l"(a), "l"(b), "l"(c));
    return d;
}
__device__ __forceinline__ float fsum2(ull v) {
    float lo, hi;
    asm("mov.b64 {%0, %1}, %2;" : "=f"(lo), "=f"(hi) : "l"(v));
    return lo + hi;
}
// 16B read-only global load as two f32x2 operands
__device__ __forceinline__ ulonglong2 ldg2(const float4* p) {
    ulonglong2 r;
    asm("ld.global.nc.v2.u64 {%0, %1}, [%2];" : "=l"(r.x), "=l"(r.y) : "l"(p));
    return r;
}
__device__ __forceinline__ float sigmf(float x) { return 1.0f / (1.0f + __expf(-x)); }
__device__ __forceinline__ float tanhf_(float x) {
    float a = fabsf(x);
    float e = __expf(-2.0f * a);
    return copysignf((1.0f - e) / (1.0f + e), x);
}

// ---------------- weight prep ----------------------------------------------------
__global__ void prep_weights(const float* __restrict__ Wih,
                             const float* __restrict__ Whh,
                             const float* __restrict__ Wt,
                             const float* __restrict__ Wo,
                             const float* __restrict__ Wg) {
    int i = blockIdx.x * blockDim.x + threadIdx.x;
    const int N1 = 32 * 768, N2 = 32 * 256, N3 = 64 * 768, N4 = 64 * 128;
    if (i < N1) {
        int kp2 = i / 768, r = i % 768;
        const float* s = Wih + (size_t)r * Isz + 4 * kp2;
        g_Wih4[i] = make_float4(s[0], s[1], s[2], s[3]);
        return;
    }
    i -= N1;
    if (i < N2) {
        int kp2 = i / 256, r = i % 256;
        const float* s = Wt + (size_t)r * Isz + 4 * kp2;
        g_Wt4[i] = make_float4(s[0], s[1], s[2], s[3]);
        return;
    }
    i -= N2;
    if (i < N3) {
        int kp2 = i / 768, r = i % 768;
        const float* s = Whh + (size_t)r * Hsz + 4 * kp2;
        g_Whh4[i] = make_float4(s[0], s[1], s[2], s[3]);
        return;
    }
    i -= N3;
    if (i < N4) {
        int kp2 = i / 128, o = i % 128;
        const float* s = (o < 64) ? (Wo + (size_t)o * Hsz) : (Wg + (size_t)(o - 64) * Hsz);
        s += 4 * kp2;
        g_Wog4[(size_t)kp2 * 128 + o] = make_float4(s[0], s[1], s[2], s[3]);
    }
}

// ---------------- phase A: input projections (independent of h) -------------------
__device__ __forceinline__ void phaseA(ull accA[4][NB], const float (*xs)[Isz], int j) {
#pragma unroll
    for (int g = 0; g < 4; ++g)
#pragma unroll
        for (int b = 0; b < NB; ++b) accA[g][b] = 0ULL;
#pragma unroll 4
    for (int kp2 = 0; kp2 < 32; ++kp2) {
        ulonglong2 wr = ldg2(&g_Wih4[kp2 * 768 + j]);
        ulonglong2 wz = ldg2(&g_Wih4[kp2 * 768 + 256 + j]);
        ulonglong2 wn = ldg2(&g_Wih4[kp2 * 768 + 512 + j]);
        ulonglong2 wt = ldg2(&g_Wt4 [kp2 * 256 + j]);
#pragma unroll
        for (int b = 0; b < NB; ++b) {
            ulonglong2 xv = *(const ulonglong2*)&xs[b][4 * kp2];
            accA[0][b] = fma2(wr.x, xv.x, accA[0][b]);
            accA[0][b] = fma2(wr.y, xv.y, accA[0][b]);
            accA[1][b] = fma2(wz.x, xv.x, accA[1][b]);
            accA[1][b] = fma2(wz.y, xv.y, accA[1][b]);
            accA[2][b] = fma2(wn.x, xv.x, accA[2][b]);
            accA[2][b] = fma2(wn.y, xv.y, accA[2][b]);
            accA[3][b] = fma2(wt.x, xv.x, accA[3][b]);
            accA[3][b] = fma2(wt.y, xv.y, accA[3][b]);
        }
    }
}

// ---------------- persistent GRU scan: 1 CTA/SM, 8 batch rows, 2 barriers/step ---
__global__ void __launch_bounds__(NTHR, 1) gru_scan(
    const float* __restrict__ x,    const float* __restrict__ h0,
    const float* __restrict__ b_ih, const float* __restrict__ b_hh,
    const float* __restrict__ bt,   const float* __restrict__ bo,
    const float* __restrict__ bg,   float* __restrict__ out)
{
    __shared__ __align__(16) float h_s[2][NB][Hsz];   // double-buffered hidden state
    __shared__ __align__(16) float v_s[NB][Hsz];      // h_new + silu(ti)
    __shared__ __align__(16) float x_s[2][NB][Isz];   // double-buffered input slice
    __shared__ __align__(16) float red[128][NB];      // proj/gate staging

    const int tid = threadIdx.x;
    const int j   = tid;                 // hidden unit owned by this thread
    const int b0  = blockIdx.x * NB;
    const int o   = tid & 127;           // output row (0..63 Wo, 64..127 Wg)
    const int bq  = (tid >> 7) * 4;      // batch quad for phase D

    { // load h0 tile
        int b = tid >> 5, k0 = (tid & 31) * 8;
        const float4* p = (const float4*)(h0 + (size_t)(b0 + b) * Hsz + k0);
        *(float4*)&h_s[0][b][k0]     = p[0];
        *(float4*)&h_s[0][b][k0 + 4] = p[1];
    }

    const float br  = b_ih[j], bz = b_ih[Hsz + j], bn = b_ih[2 * Hsz + j];
    const float hbr = b_hh[j], hbz = b_hh[Hsz + j], hbn = b_hh[2 * Hsz + j];
    const float btj = bt[j];
    float boT = 0.0f, bgT = 0.0f;
    if (tid < 64) { boT = bo[tid]; bgT = bg[tid]; }

    float oacc[NB];
#pragma unroll
    for (int b = 0; b < NB; ++b) oacc[b] = 0.0f;

    // prologue: stage x(0), compute A(0), stage x(1)
    {
        int b = tid >> 5, k0 = (tid & 31) * 4;
        const float* xb = x + (size_t)(b0 + b) * Tsz * Isz + k0;
        *(float4*)&x_s[0][b][k0] = *(const float4*)(xb);
        __syncthreads();
        // stage x(1) (read after S3(0) -> ordering OK)
        *(float4*)&x_s[1][b][k0] = *(const float4*)(xb + Isz);
    }

    ull accA[4][NB];
    phaseA(accA, x_s[0], j);

    for (int t = 0; t < Tsz; ++t) {
        const int p = t & 1;

        // ---- Phase B: hh = W_hh . h(t-1), K=256 (reads h_s[p]) ----
        ull hR[NB], hZ[NB], hN[NB];
#pragma unroll
        for (int b = 0; b < NB; ++b) { hR[b] = 0ULL; hZ[b] = 0ULL; hN[b] = 0ULL; }
#pragma unroll 4
        for (int kp2 = 0; kp2 < 64; ++kp2) {
            ulonglong2 wr = ldg2(&g_Whh4[kp2 * 768 + j]);
            ulonglong2 wz = ldg2(&g_Whh4[kp2 * 768 + 256 + j]);
            ulonglong2 wn = ldg2(&g_Whh4[kp2 * 768 + 512 + j]);
#pragma unroll
            for (int b = 0; b < NB; ++b) {
                ulonglong2 hv = *(const ulonglong2*)&h_s[p][b][4 * kp2];
                hR[b] = fma2(wr.x, hv.x, hR[b]);
                hR[b] = fma2(wr.y, hv.y, hR[b]);
                hZ[b] = fma2(wz.x, hv.x, hZ[b]);
                hZ[b] = fma2(wz.y, hv.y, hZ[b]);
                hN[b] = fma2(wn.x, hv.x, hN[b]);
                hN[b] = fma2(wn.y, hv.y, hN[b]);
            }
        }

        // ---- Phase C: gates + state update (writes h_s[p^1], v_s) ----
#pragma unroll
        for (int b = 0; b < NB; ++b) {
            float xr = fsum2(accA[0][b]) + br;
            float xz = fsum2(accA[1][b]) + bz;
            float xn = fsum2(accA[2][b]) + bn;
            float xt = fsum2(accA[3][b]) + btj;
            float r  = sigmf(xr + fsum2(hR[b]) + hbr);
            float z  = sigmf(xz + fsum2(hZ[b]) + hbz);
            float n  = tanhf_(xn + r * (fsum2(hN[b]) + hbn));
            float hp = h_s[p][b][j];
            float hn2 = n + z * (hp - n);
            h_s[p ^ 1][b][j] = hn2;
            v_s[b][j] = hn2 + xt * sigmf(xt);   // h_new + silu(ti)
        }
        __syncthreads();  // S3: h(t), v ready

        // ---- Phase D: full-K dots, 4 per thread (no split-K) ----
        {
            const float* basep = (o < 64) ? &v_s[0][0] : &h_s[p ^ 1][0][0];
            ull acc0 = 0ULL, acc1 = 0ULL, acc2 = 0ULL, acc3 = 0ULL;
#pragma unroll 4
            for (int kp2 = 0; kp2 < 64; ++kp2) {
                ulonglong2 w = ldg2(&g_Wog4[kp2 * 128 + o]);
                const float* sp = basep + (size_t)bq * Hsz + 4 * kp2;
                ulonglong2 s0 = *(const ulonglong2*)(sp);
                ulonglong2 s1 = *(const ulonglong2*)(sp + Hsz);
                ulonglong2 s2 = *(const ulonglong2*)(sp + 2 * Hsz);
                ulonglong2 s3 = *(const ulonglong2*)(sp + 3 * Hsz);
                acc0 = fma2(w.x, s0.x, acc0); acc0 = fma2(w.y, s0.y, acc0);
                acc1 = fma2(w.x, s1.x, acc1); acc1 = fma2(w.y, s1.y, acc1);
                acc2 = fma2(w.x, s2.x, acc2); acc2 = fma2(w.y, s2.y, acc2);
                acc3 = fma2(w.x, s3.x, acc3); acc3 = fma2(w.y, s3.y, acc3);
            }
            *(float4*)&red[o][bq] =
                make_float4(fsum2(acc0), fsum2(acc1), fsum2(acc2), fsum2(acc3));
        }

        // ---- Phase A(t+1): input projections for next step (overlaps D) ----
        if (t + 1 < Tsz) phaseA(accA, x_s[(t + 1) & 1], j);

        // ---- stage x(t+2) into the buffer A(t) just finished with ----
        if (t + 2 < Tsz) {
            int b = tid >> 5, k0 = (tid & 31) * 4;
            *(float4*)&x_s[p][b][k0] =
                *(const float4*)(x + ((size_t)(b0 + b) * Tsz + t + 2) * Isz + k0);
        }
        __syncthreads();  // S_red: red + staged x visible

        // ---- finalize: out accumulation ----
        if (tid < 64) {
            float4 pr0 = *(const float4*)&red[tid][0];
            float4 pr1 = *(const float4*)&red[tid][4];
            float4 gt0 = *(const float4*)&red[64 + tid][0];
            float4 gt1 = *(const float4*)&red[64 + tid][4];
            oacc[0] += (pr0.x + boT) * sigmf(gt0.x + bgT);
            oacc[1] += (pr0.y + boT) * sigmf(gt0.y + bgT);
            oacc[2] += (pr0.z + boT) * sigmf(gt0.z + bgT);
            oacc[3] += (pr0.w + boT) * sigmf(gt0.w + bgT);
            oacc[4] += (pr1.x + boT) * sigmf(gt1.x + bgT);
            oacc[5] += (pr1.y + boT) * sigmf(gt1.y + bgT);
            oacc[6] += (pr1.z + boT) * sigmf(gt1.z + bgT);
            oacc[7] += (pr1.w + boT) * sigmf(gt1.w + bgT);
        }
    }

    if (tid < 64) {
        const float inv = 1.0f / (float)Tsz;
#pragma unroll
        for (int b = 0; b < NB; ++b)
            out[(size_t)(b0 + b) * Osz + tid] = oacc[b] * inv;
    }
}

// ---------------- launch ---------------------------------------------------------
extern "C" void kernel_launch(void* const* d_in, const int* in_sizes, int n_in,
                              void* d_out, int out_size) {
    const float* x    = (const float*)d_in[0];
    const float* h0   = (const float*)d_in[1];
    const float* W_ih = (const float*)d_in[2];
    const float* b_ih = (const float*)d_in[3];
    const float* W_hh = (const float*)d_in[4];
    const float* b_hh = (const float*)d_in[5];
    const float* Wt   = (const float*)d_in[6];
    const float* bt   = (const float*)d_in[7];
    const float* Wo   = (const float*)d_in[8];
    const float* bo   = (const float*)d_in[9];
    const float* Wg   = (const float*)d_in[10];
    const float* bg   = (const float*)d_in[11];
    float* out = (float*)d_out;

    const int total = 32 * 768 + 32 * 256 + 64 * 768 + 64 * 128;  // 90112
    prep_weights<<<(total + 255) / 256, 256>>>(W_ih, W_hh, Wt, Wo, Wg);
    gru_scan<<<NCTA, NTHR>>>(x, h0, b_ih, b_hh, bt, bo, bg, out);
}